// round 13
// baseline (speedup 1.0000x reference)
#include <cuda_runtime.h>

// ---------------- problem constants ----------------
#define B_    16
#define SQ_   1024
#define SE_   1024
#define CIN   256
#define H_    8
#define HD    512         // H*DK = H*DV
#define MTOT  16384       // B*SQ = B*SE
#define XN    (B_ * SE_ * CIN)   // elements in x / q

// ---------------- device scratch (allocation-free rule) ----------------
__device__ float g_Q[(size_t)MTOT * HD];
__device__ float g_K[(size_t)MTOT * HD];
__device__ float g_V[(size_t)MTOT * HD];
__device__ float g_O[(size_t)MTOT * HD];   // head-major concat, tf32-rounded
__device__ float g_P[(size_t)MTOT * CIN];  // pre-BN (fp32)
__device__ float g_xq[(size_t)XN];         // tf32(x)
__device__ float g_qq[(size_t)XN];         // tf32(0.125*q)
__device__ float g_wq[HD * CIN];
__device__ float g_wk[HD * CIN];
__device__ float g_wv[HD * CIN];
__device__ float g_wp[CIN * HD];
__device__ float g_ps [128 * CIN];
__device__ float g_ps2[128 * CIN];
__device__ float g_scale[CIN];
__device__ float g_bias [CIN];

// ---------------- tf32 / async helpers ----------------
__device__ __forceinline__ unsigned f2tf(float f) {
    unsigned r; asm("cvt.rna.tf32.f32 %0, %1;" : "=r"(r) : "f"(f)); return r;
}
__device__ __forceinline__ float tf(float f) { return __uint_as_float(f2tf(f)); }

__device__ __forceinline__ void mma8(float c[4], const unsigned a[4], const unsigned b[2]) {
    asm volatile("mma.sync.aligned.m16n8k8.row.col.f32.tf32.tf32.f32 "
                 "{%0,%1,%2,%3}, {%4,%5,%6,%7}, {%8,%9}, {%0,%1,%2,%3};\n"
                 : "+f"(c[0]), "+f"(c[1]), "+f"(c[2]), "+f"(c[3])
                 : "r"(a[0]), "r"(a[1]), "r"(a[2]), "r"(a[3]), "r"(b[0]), "r"(b[1]));
}

__device__ __forceinline__ void cp16(float* dst, const float* src) {
    unsigned d = (unsigned)__cvta_generic_to_shared(dst);
    asm volatile("cp.async.cg.shared.global [%0], [%1], 16;" :: "r"(d), "l"(src) : "memory");
}
#define CP_COMMIT() asm volatile("cp.async.commit_group;" ::: "memory")
#define CP_WAIT0()  asm volatile("cp.async.wait_group 0;" ::: "memory")

// ---------------- fused producer-side tf32 quantization (1 launch) ----------------
#define NX4 (XN / 4)            // 1048576 float4 per activation tensor
#define NW4 (HD * CIN / 4)      // 32768 float4 per weight tensor
__global__ void quant_all(const float4* __restrict__ q,  const float4* __restrict__ x,
                          const float4* __restrict__ wq, const float4* __restrict__ wk,
                          const float4* __restrict__ wv, const float4* __restrict__ wp,
                          float4* __restrict__ oq, float4* __restrict__ ox,
                          float4* __restrict__ owq, float4* __restrict__ owk,
                          float4* __restrict__ owv, float4* __restrict__ owp) {
    int i = blockIdx.x * 256 + threadIdx.x;
    const float4* src; float4* dst; float sc = 1.0f; int off;
    if (i < NX4)                    { src = q;  dst = oq;  off = i;           sc = 0.125f; }
    else if (i < 2 * NX4)           { src = x;  dst = ox;  off = i - NX4; }
    else if (i < 2 * NX4 + NW4)     { src = wq; dst = owq; off = i - 2 * NX4; }
    else if (i < 2 * NX4 + 2 * NW4) { src = wk; dst = owk; off = i - 2 * NX4 - NW4; }
    else if (i < 2 * NX4 + 3 * NW4) { src = wv; dst = owv; off = i - 2 * NX4 - 2 * NW4; }
    else                            { src = wp; dst = owp; off = i - 2 * NX4 - 3 * NW4; }
    float4 v = src[off];
    dst[off] = make_float4(tf(v.x * sc), tf(v.y * sc), tf(v.z * sc), tf(v.w * sc));
}

// ---------------- tf32 NT GEMM core, cp.async double-buffered, paired-k LDS.64 ----
// C[M][N] = A[M][K] * W[N][K]^T ; tile 128x64, K-chunk 64, 256 threads.
// QOUT: tf32-round outputs. BN: emit per-block deterministic BN partial sums.
#define GSTR 72
template<bool QOUT, bool BN>
__device__ __forceinline__ void gemm_core(const float* __restrict__ A,
                                          const float* __restrict__ W,
                                          float* __restrict__ C, int N, int K,
                                          int m0, int n0, int by, float* sm) {
    float* As = sm;                          // [2][128*72]
    float* Bs = sm + 2 * 128 * GSTR;         // [2][64*72]
    const int tid = threadIdx.x, lane = tid & 31, warp = tid >> 5;
    const int g = lane >> 2, tig = lane & 3;
    const int wrow = warp << 4;

    auto load = [&](int buf, int kt) {
        float* da = As + buf * 128 * GSTR;
        float* db = Bs + buf * 64 * GSTR;
        for (int i = tid; i < 2048; i += 256) {
            int r = i >> 4, c4 = (i & 15) << 2;
            cp16(da + r * GSTR + c4, A + (size_t)(m0 + r) * K + kt + c4);
        }
        for (int i = tid; i < 1024; i += 256) {
            int r = i >> 4, c4 = (i & 15) << 2;
            cp16(db + r * GSTR + c4, W + (size_t)(n0 + r) * K + kt + c4);
        }
    };

    load(0, 0); CP_COMMIT();

    float acc[8][4];
#pragma unroll
    for (int nt = 0; nt < 8; nt++)
#pragma unroll
        for (int j = 0; j < 4; j++) acc[nt][j] = 0.f;

    const int nk = K >> 6;
    for (int ki = 0; ki < nk; ki++) {
        CP_WAIT0();
        __syncthreads();
        if (ki + 1 < nk) { load((ki + 1) & 1, (ki + 1) << 6); CP_COMMIT(); }
        const float* as = As + (ki & 1) * 128 * GSTR;
        const float* bs = Bs + (ki & 1) * 64 * GSTR;
#pragma unroll
        for (int kk = 0; kk < 64; kk += 8) {
            // paired-k A fragment: a[0],a[2] = row g, logical k 2tig,2tig+1
            unsigned a[4];
            float2 a0 = *(const float2*)(as + (wrow + g) * GSTR + kk + 2 * tig);
            float2 a1 = *(const float2*)(as + (wrow + g + 8) * GSTR + kk + 2 * tig);
            a[0] = __float_as_uint(a0.x); a[2] = __float_as_uint(a0.y);
            a[1] = __float_as_uint(a1.x); a[3] = __float_as_uint(a1.y);
#pragma unroll
            for (int nt = 0; nt < 8; nt++) {
                unsigned b[2];
                float2 bv = *(const float2*)(bs + ((nt << 3) + g) * GSTR + kk + 2 * tig);
                b[0] = __float_as_uint(bv.x); b[1] = __float_as_uint(bv.y);
                mma8(acc[nt], a, b);
            }
        }
    }
    float* c0 = C + (size_t)(m0 + wrow + g) * N + n0;
    float* c1 = c0 + (size_t)8 * N;
#pragma unroll
    for (int nt = 0; nt < 8; nt++) {
        if (QOUT) {
            *(float2*)(c0 + (nt << 3) + (tig << 1)) = make_float2(tf(acc[nt][0]), tf(acc[nt][1]));
            *(float2*)(c1 + (nt << 3) + (tig << 1)) = make_float2(tf(acc[nt][2]), tf(acc[nt][3]));
        } else {
            *(float2*)(c0 + (nt << 3) + (tig << 1)) = make_float2(acc[nt][0], acc[nt][1]);
            *(float2*)(c1 + (nt << 3) + (tig << 1)) = make_float2(acc[nt][2], acc[nt][3]);
        }
    }

    if (BN) {
        // deterministic per-block BN partials over this block's 128 rows.
        // thread col partials (16 cols each: nt*8 + 2tig + j), rows g and g+8
        float ps[16], ps2[16];
#pragma unroll
        for (int nt = 0; nt < 8; nt++)
#pragma unroll
            for (int j = 0; j < 2; j++) {
                float v0 = acc[nt][j], v1 = acc[nt][j + 2];
                ps [nt * 2 + j] = v0 + v1;
                ps2[nt * 2 + j] = v0 * v0 + v1 * v1;
            }
        // reduce over g (lanes differing by 4,8,16) — fixed order, deterministic
#pragma unroll
        for (int off = 4; off < 32; off <<= 1)
#pragma unroll
            for (int i = 0; i < 16; i++) {
                ps [i] += __shfl_xor_sync(0xffffffffu, ps [i], off);
                ps2[i] += __shfl_xor_sync(0xffffffffu, ps2[i], off);
            }
        __syncthreads();               // all warps done reading As/Bs; reuse sm
        float2* red = (float2*)sm;     // [8 warps][64 cols]
        if (g == 0) {
#pragma unroll
            for (int nt = 0; nt < 8; nt++)
#pragma unroll
                for (int j = 0; j < 2; j++) {
                    int col = nt * 8 + 2 * tig + j;
                    red[warp * 64 + col] = make_float2(ps[nt * 2 + j], ps2[nt * 2 + j]);
                }
        }
        __syncthreads();
        if (tid < 64) {
            float s = 0.f, s2 = 0.f;
#pragma unroll
            for (int w = 0; w < 8; w++) {
                float2 v = red[w * 64 + tid];
                s += v.x; s2 += v.y;
            }
            g_ps [by * CIN + n0 + tid] = s;
            g_ps2[by * CIN + n0 + tid] = s2;
        }
    }
}

// merged projections: z=0 Q, z=1 K, z=2 V
__global__ __launch_bounds__(256) void gemm_proj(const float* __restrict__ qq,
                                                 const float* __restrict__ xq,
                                                 const float* __restrict__ wq,
                                                 const float* __restrict__ wk,
                                                 const float* __restrict__ wv,
                                                 float* __restrict__ Q,
                                                 float* __restrict__ K,
                                                 float* __restrict__ V) {
    extern __shared__ float sm[];
    const float* A; const float* W; float* C;
    if (blockIdx.z == 0)      { A = qq; W = wq; C = Q; }
    else if (blockIdx.z == 1) { A = xq; W = wk; C = K; }
    else                      { A = xq; W = wv; C = V; }
    gemm_core<true, false>(A, W, C, HD, CIN, blockIdx.y << 7, blockIdx.x << 6,
                           blockIdx.y, sm);
}

// output projection + fused BN partial sums
__global__ __launch_bounds__(256) void gemm_out(const float* __restrict__ A,
                                                const float* __restrict__ W,
                                                float* __restrict__ C) {
    extern __shared__ float sm[];
    gemm_core<false, true>(A, W, C, CIN, HD, blockIdx.y << 7, blockIdx.x << 6,
                           blockIdx.y, sm);
}

// ---------------- flash attention, cp.async double-buffered, paired-k S-phase ----
#define QSTR 68     // Qs/Ps stride (keeps PV 32-bit loads conflict-free)
#define KSTR 72     // Ks stride (keeps paired 64-bit loads conflict-free)
#define VSTR 72
__global__ __launch_bounds__(256) void attn2(const float* __restrict__ Q,
                                             const float* __restrict__ K,
                                             const float* __restrict__ V,
                                             float* __restrict__ O) {
    extern __shared__ float sm[];
    float* Qs = sm;                            // [128*68]; reused as Ps after hoist
    float* Kb = sm + 128 * QSTR;               // [2][64*72]
    float* Vb = Kb + 2 * 64 * KSTR;            // [2][64*72]
    float* Ps = Qs;

    const int tid = threadIdx.x, lane = tid & 31, warp = tid >> 5;
    const int g = lane >> 2, tig = lane & 3;
    const int b = blockIdx.z, h = blockIdx.y, q0 = blockIdx.x << 7;
    const int wrow = warp << 4;

    const float* Qb = Q + ((size_t)(b * SQ_ + q0)) * HD + h * 64;
    const float* Kbase = K + ((size_t)b * SE_) * HD + h * 64;
    const float* Vbase = V + ((size_t)b * SE_) * HD + h * 64;

    auto loadKV = [&](int buf, int t0) {
        float* dk = Kb + buf * 64 * KSTR;
        float* dv = Vb + buf * 64 * VSTR;
        for (int i = tid; i < 1024; i += 256) {
            int r = i >> 4, c4 = (i & 15) << 2;
            cp16(dk + r * KSTR + c4, Kbase + (size_t)(t0 + r) * HD + c4);
            cp16(dv + r * VSTR + c4, Vbase + (size_t)(t0 + r) * HD + c4);
        }
    };

    loadKV(0, 0); CP_COMMIT();

    // stage Q (already tf32-rounded + pre-scaled), hoist paired-k fragments
    for (int i = tid; i < 2048; i += 256) {
        int r = i >> 4, c4 = (i & 15) << 2;
        *(float4*)(Qs + r * QSTR + c4) = *(const float4*)(Qb + (size_t)r * HD + c4);
    }
    __syncthreads();

    unsigned qf[8][4];
#pragma unroll
    for (int kc = 0; kc < 8; kc++) {
        float2 v0 = *(const float2*)(Qs + (wrow + g) * QSTR + (kc << 3) + 2 * tig);
        float2 v1 = *(const float2*)(Qs + (wrow + g + 8) * QSTR + (kc << 3) + 2 * tig);
        qf[kc][0] = __float_as_uint(v0.x); qf[kc][2] = __float_as_uint(v0.y);
        qf[kc][1] = __float_as_uint(v1.x); qf[kc][3] = __float_as_uint(v1.y);
    }

    float mr0 = -1e30f, mr1 = -1e30f, l0 = 0.f, l1 = 0.f;
    float o[8][4];
#pragma unroll
    for (int nt = 0; nt < 8; nt++)
#pragma unroll
        for (int j = 0; j < 4; j++) o[nt][j] = 0.f;

    for (int ti = 0; ti < SE_ / 64; ti++) {
        CP_WAIT0();
        __syncthreads();   // KV[ti] visible; all warps done with other buf and Ps/Qs
        if (ti + 1 < SE_ / 64) { loadKV((ti + 1) & 1, (ti + 1) << 6); CP_COMMIT(); }
        const float* ks = Kb + (ti & 1) * 64 * KSTR;
        const float* vs = Vb + (ti & 1) * 64 * VSTR;

        // S = Q K^T, paired-k B fragments (LDS.64)
        float s[8][4];
#pragma unroll
        for (int nt = 0; nt < 8; nt++)
#pragma unroll
            for (int j = 0; j < 4; j++) s[nt][j] = 0.f;
#pragma unroll
        for (int kc = 0; kc < 8; kc++) {
#pragma unroll
            for (int nt = 0; nt < 8; nt++) {
                unsigned bb[2];
                float2 bv = *(const float2*)(ks + ((nt << 3) + g) * KSTR + (kc << 3) + 2 * tig);
                bb[0] = __float_as_uint(bv.x); bb[1] = __float_as_uint(bv.y);
                mma8(s[nt], qf[kc], bb);
            }
        }

        // online softmax (rows wrow+g and wrow+g+8)
        float mx0 = -1e30f, mx1 = -1e30f;
#pragma unroll
        for (int nt = 0; nt < 8; nt++) {
            mx0 = fmaxf(mx0, fmaxf(s[nt][0], s[nt][1]));
            mx1 = fmaxf(mx1, fmaxf(s[nt][2], s[nt][3]));
        }
        mx0 = fmaxf(mx0, __shfl_xor_sync(0xffffffffu, mx0, 1));
        mx0 = fmaxf(mx0, __shfl_xor_sync(0xffffffffu, mx0, 2));
        mx1 = fmaxf(mx1, __shfl_xor_sync(0xffffffffu, mx1, 1));
        mx1 = fmaxf(mx1, __shfl_xor_sync(0xffffffffu, mx1, 2));
        float nm0 = fmaxf(mr0, mx0), nm1 = fmaxf(mr1, mx1);
        float corr0 = __expf(mr0 - nm0), corr1 = __expf(mr1 - nm1);
        mr0 = nm0; mr1 = nm1;
        float sum0 = 0.f, sum1 = 0.f;
#pragma unroll
        for (int nt = 0; nt < 8; nt++) {
            s[nt][0] = __expf(s[nt][0] - nm0); sum0 += s[nt][0];
            s[nt][1] = __expf(s[nt][1] - nm0); sum0 += s[nt][1];
            s[nt][2] = __expf(s[nt][2] - nm1); sum1 += s[nt][2];
            s[nt][3] = __expf(s[nt][3] - nm1); sum1 += s[nt][3];
        }
        sum0 += __shfl_xor_sync(0xffffffffu, sum0, 1);
        sum0 += __shfl_xor_sync(0xffffffffu, sum0, 2);
        sum1 += __shfl_xor_sync(0xffffffffu, sum1, 1);
        sum1 += __shfl_xor_sync(0xffffffffu, sum1, 2);
        l0 = l0 * corr0 + sum0;
        l1 = l1 * corr1 + sum1;
#pragma unroll
        for (int nt = 0; nt < 8; nt++) {
            o[nt][0] *= corr0; o[nt][1] *= corr0;
            o[nt][2] *= corr1; o[nt][3] *= corr1;
        }

        // P -> smem (tf32 round), own 16 rows, consumed in-warp
        {
            float* p0 = Ps + (wrow + g) * QSTR + (tig << 1);
            float* p1 = p0 + 8 * QSTR;
#pragma unroll
            for (int nt = 0; nt < 8; nt++) {
                *(float2*)(p0 + (nt << 3)) = make_float2(tf(s[nt][0]), tf(s[nt][1]));
                *(float2*)(p1 + (nt << 3)) = make_float2(tf(s[nt][2]), tf(s[nt][3]));
            }
        }
        __syncwarp();

        // O += P V (standard k mapping; V fragments span rows -> unpaired)
#pragma unroll
        for (int kc = 0; kc < 8; kc++) {
            unsigned a[4];
            const float* ap = Ps + (wrow + g) * QSTR + (kc << 3) + tig;
            a[0] = __float_as_uint(ap[0]);
            a[1] = __float_as_uint(ap[8 * QSTR]);
            a[2] = __float_as_uint(ap[4]);
            a[3] = __float_as_uint(ap[8 * QSTR + 4]);
#pragma unroll
            for (int nt = 0; nt < 8; nt++) {
                unsigned bb[2];
                const float* bp = vs + ((kc << 3) + tig) * VSTR + (nt << 3) + g;
                bb[0] = __float_as_uint(bp[0]);
                bb[1] = __float_as_uint(bp[4 * VSTR]);
                mma8(o[nt], a, bb);
            }
        }
    }

    const float il0 = 1.f / l0, il1 = 1.f / l1;
    float* o0 = O + ((size_t)(b * SQ_ + q0 + wrow + g)) * HD + h * 64;
    float* o1 = o0 + (size_t)8 * HD;
#pragma unroll
    for (int nt = 0; nt < 8; nt++) {
        *(float2*)(o0 + (nt << 3) + (tig << 1)) = make_float2(tf(o[nt][0] * il0), tf(o[nt][1] * il0));
        *(float2*)(o1 + (nt << 3) + (tig << 1)) = make_float2(tf(o[nt][2] * il1), tf(o[nt][3] * il1));
    }
}

// ---------------- BN finalize + apply ----------------
__global__ void bn_final(const float* __restrict__ gamma, const float* __restrict__ beta) {
    int c = threadIdx.x;
    float s = 0.f, s2 = 0.f;
#pragma unroll 4
    for (int b2 = 0; b2 < 128; b2++) {
        s  += g_ps [b2 * CIN + c];
        s2 += g_ps2[b2 * CIN + c];
    }
    const float inv = 1.f / (float)MTOT;
    float mean = s * inv;
    float var  = s2 * inv - mean * mean;
    float rstd = rsqrtf(var + 1e-5f);
    float sc = rstd * gamma[c];
    g_scale[c] = sc;
    g_bias [c] = beta[c] - mean * sc;
}

__global__ void bn_apply(float* __restrict__ out) {
    __shared__ float ssc[CIN], sbi[CIN];
    ssc[threadIdx.x] = g_scale[threadIdx.x];
    sbi[threadIdx.x] = g_bias [threadIdx.x];
    __syncthreads();
    size_t i = (size_t)blockIdx.x * 256 + threadIdx.x;
    float4 v = *(const float4*)(g_P + i * 4);
    int c = (int)((i * 4) & (CIN - 1));
    float r[4] = {v.x, v.y, v.z, v.w};
#pragma unroll
    for (int u = 0; u < 4; u++) {
        float y = r[u] * ssc[c + u] + sbi[c + u];
        r[u] = y >= 0.f ? y : 0.01f * y;
    }
    *(float4*)(out + i * 4) = make_float4(r[0], r[1], r[2], r[3]);
}

// ---------------- launch ----------------
extern "C" void kernel_launch(void* const* d_in, const int* in_sizes, int n_in,
                              void* d_out, int out_size) {
    const float* x     = (const float*)d_in[0];
    const float* q     = (const float*)d_in[1];
    const float* Wq    = (const float*)d_in[2];
    const float* Wk    = (const float*)d_in[3];
    const float* Wv    = (const float*)d_in[4];
    const float* Wp    = (const float*)d_in[5];
    const float* gamma = (const float*)d_in[6];
    const float* beta  = (const float*)d_in[7];
    float* out = (float*)d_out;

    void *pQ, *pK, *pV, *pO, *pP, *pxq, *pqq, *pwq, *pwk, *pwv, *pwp;
    cudaGetSymbolAddress(&pQ, g_Q);   cudaGetSymbolAddress(&pK, g_K);
    cudaGetSymbolAddress(&pV, g_V);   cudaGetSymbolAddress(&pO, g_O);
    cudaGetSymbolAddress(&pP, g_P);   cudaGetSymbolAddress(&pxq, g_xq);
    cudaGetSymbolAddress(&pqq, g_qq); cudaGetSymbolAddress(&pwq, g_wq);
    cudaGetSymbolAddress(&pwk, g_wk); cudaGetSymbolAddress(&pwv, g_wv);
    cudaGetSymbolAddress(&pwp, g_wp);

    const int gemm_smem = (2 * 128 * GSTR + 2 * 64 * GSTR) * 4;              // 110592
    const int attn_smem = (128 * QSTR + 2 * 64 * KSTR + 2 * 64 * VSTR) * 4;  // 108544
    cudaFuncSetAttribute(gemm_proj, cudaFuncAttributeMaxDynamicSharedMemorySize, gemm_smem);
    cudaFuncSetAttribute(gemm_out,  cudaFuncAttributeMaxDynamicSharedMemorySize, gemm_smem);
    cudaFuncSetAttribute(attn2,     cudaFuncAttributeMaxDynamicSharedMemorySize, attn_smem);

    // single fused tf32 quantization pass (q folds 1/sqrt(DK) — exact)
    quant_all<<<(2 * NX4 + 4 * NW4) / 256, 256>>>(
        (const float4*)q, (const float4*)x, (const float4*)Wq, (const float4*)Wk,
        (const float4*)Wv, (const float4*)Wp,
        (float4*)pqq, (float4*)pxq, (float4*)pwq, (float4*)pwk,
        (float4*)pwv, (float4*)pwp);

    // merged Q/K/V projections: [16384,256] x [512,256]^T -> [16384,512]
    gemm_proj<<<dim3(HD / 64, MTOT / 128, 3), 256, gemm_smem>>>(
        (const float*)pqq, (const float*)pxq,
        (const float*)pwq, (const float*)pwk, (const float*)pwv,
        (float*)pQ, (float*)pK, (float*)pV);

    // attention
    attn2<<<dim3(SQ_ / 128, H_, B_), 256, attn_smem>>>(
        (const float*)pQ, (const float*)pK, (const float*)pV, (float*)pO);

    // output projection + fused BN partials: [16384,512] x [256,512]^T -> [16384,256]
    gemm_out<<<dim3(CIN / 64, MTOT / 128), 256, gemm_smem>>>(
        (const float*)pO, (const float*)pwp, (float*)pP);

    // BN finalize + apply
    bn_final<<<1, 256>>>(gamma, beta);
    bn_apply<<<(MTOT * CIN) / (4 * 256), 256>>>(out);
}

// round 14
// speedup vs baseline: 1.0063x; 1.0063x over previous
#include <cuda_runtime.h>

// ---------------- problem constants ----------------
#define B_    16
#define SQ_   1024
#define SE_   1024
#define CIN   256
#define H_    8
#define HD    512         // H*DK = H*DV
#define MTOT  16384       // B*SQ = B*SE
#define XN    (B_ * SE_ * CIN)   // elements in x / q

// ---------------- device scratch (allocation-free rule) ----------------
__device__ float g_Q[(size_t)MTOT * HD];
__device__ float g_K[(size_t)MTOT * HD];
__device__ float g_V[(size_t)MTOT * HD];
__device__ float g_O[(size_t)MTOT * HD];   // head-major concat, tf32-rounded
__device__ float g_P[(size_t)MTOT * CIN];  // pre-BN (fp32)
__device__ float g_xq[(size_t)XN];         // tf32(x)
__device__ float g_qq[(size_t)XN];         // tf32(0.125*q)
__device__ float g_wq[HD * CIN];
__device__ float g_wk[HD * CIN];
__device__ float g_wv[HD * CIN];
__device__ float g_wp[CIN * HD];
__device__ float g_ps [128 * CIN];
__device__ float g_ps2[128 * CIN];
__device__ float g_scale[CIN];
__device__ float g_bias [CIN];

// ---------------- tf32 / async helpers ----------------
__device__ __forceinline__ unsigned f2tf(float f) {
    unsigned r; asm("cvt.rna.tf32.f32 %0, %1;" : "=r"(r) : "f"(f)); return r;
}
__device__ __forceinline__ float tf(float f) { return __uint_as_float(f2tf(f)); }

__device__ __forceinline__ void mma8(float c[4], const unsigned a[4], const unsigned b[2]) {
    asm volatile("mma.sync.aligned.m16n8k8.row.col.f32.tf32.tf32.f32 "
                 "{%0,%1,%2,%3}, {%4,%5,%6,%7}, {%8,%9}, {%0,%1,%2,%3};\n"
                 : "+f"(c[0]), "+f"(c[1]), "+f"(c[2]), "+f"(c[3])
                 : "r"(a[0]), "r"(a[1]), "r"(a[2]), "r"(a[3]), "r"(b[0]), "r"(b[1]));
}

__device__ __forceinline__ void cp16(float* dst, const float* src) {
    unsigned d = (unsigned)__cvta_generic_to_shared(dst);
    asm volatile("cp.async.cg.shared.global [%0], [%1], 16;" :: "r"(d), "l"(src) : "memory");
}
#define CP_COMMIT() asm volatile("cp.async.commit_group;" ::: "memory")
#define CP_WAIT0()  asm volatile("cp.async.wait_group 0;" ::: "memory")

// ---------------- fused producer-side tf32 quantization (1 launch) ----------------
#define NX4 (XN / 4)            // 1048576 float4 per activation tensor
#define NW4 (HD * CIN / 4)      // 32768 float4 per weight tensor
__global__ void quant_all(const float4* __restrict__ q,  const float4* __restrict__ x,
                          const float4* __restrict__ wq, const float4* __restrict__ wk,
                          const float4* __restrict__ wv, const float4* __restrict__ wp,
                          float4* __restrict__ oq, float4* __restrict__ ox,
                          float4* __restrict__ owq, float4* __restrict__ owk,
                          float4* __restrict__ owv, float4* __restrict__ owp) {
    int i = blockIdx.x * 256 + threadIdx.x;
    const float4* src; float4* dst; float sc = 1.0f; int off;
    if (i < NX4)                    { src = q;  dst = oq;  off = i;           sc = 0.125f; }
    else if (i < 2 * NX4)           { src = x;  dst = ox;  off = i - NX4; }
    else if (i < 2 * NX4 + NW4)     { src = wq; dst = owq; off = i - 2 * NX4; }
    else if (i < 2 * NX4 + 2 * NW4) { src = wk; dst = owk; off = i - 2 * NX4 - NW4; }
    else if (i < 2 * NX4 + 3 * NW4) { src = wv; dst = owv; off = i - 2 * NX4 - 2 * NW4; }
    else                            { src = wp; dst = owp; off = i - 2 * NX4 - 3 * NW4; }
    float4 v = src[off];
    dst[off] = make_float4(tf(v.x * sc), tf(v.y * sc), tf(v.z * sc), tf(v.w * sc));
}

// ---------------- tf32 NT GEMM core, cp.async double-buffered, paired-k LDS.64 ----
// C[M][N] = A[M][K] * W[N][K]^T ; tile 128x64, K-chunk 64, 256 threads.
// QOUT: tf32-round outputs. BN: emit per-block deterministic BN partial sums.
#define GSTR 72
template<bool QOUT, bool BN>
__device__ __forceinline__ void gemm_core(const float* __restrict__ A,
                                          const float* __restrict__ W,
                                          float* __restrict__ C, int N, int K,
                                          int m0, int n0, int by, float* sm) {
    float* As = sm;                          // [2][128*72]
    float* Bs = sm + 2 * 128 * GSTR;         // [2][64*72]
    const int tid = threadIdx.x, lane = tid & 31, warp = tid >> 5;
    const int g = lane >> 2, tig = lane & 3;
    const int wrow = warp << 4;

    auto load = [&](int buf, int kt) {
        float* da = As + buf * 128 * GSTR;
        float* db = Bs + buf * 64 * GSTR;
        for (int i = tid; i < 2048; i += 256) {
            int r = i >> 4, c4 = (i & 15) << 2;
            cp16(da + r * GSTR + c4, A + (size_t)(m0 + r) * K + kt + c4);
        }
        for (int i = tid; i < 1024; i += 256) {
            int r = i >> 4, c4 = (i & 15) << 2;
            cp16(db + r * GSTR + c4, W + (size_t)(n0 + r) * K + kt + c4);
        }
    };

    load(0, 0); CP_COMMIT();

    float acc[8][4];
#pragma unroll
    for (int nt = 0; nt < 8; nt++)
#pragma unroll
        for (int j = 0; j < 4; j++) acc[nt][j] = 0.f;

    const int nk = K >> 6;
    for (int ki = 0; ki < nk; ki++) {
        CP_WAIT0();
        __syncthreads();
        if (ki + 1 < nk) { load((ki + 1) & 1, (ki + 1) << 6); CP_COMMIT(); }
        const float* as = As + (ki & 1) * 128 * GSTR;
        const float* bs = Bs + (ki & 1) * 64 * GSTR;
#pragma unroll
        for (int kk = 0; kk < 64; kk += 8) {
            // paired-k A fragment: a[0],a[2] = row g, logical k 2tig,2tig+1
            unsigned a[4];
            float2 a0 = *(const float2*)(as + (wrow + g) * GSTR + kk + 2 * tig);
            float2 a1 = *(const float2*)(as + (wrow + g + 8) * GSTR + kk + 2 * tig);
            a[0] = __float_as_uint(a0.x); a[2] = __float_as_uint(a0.y);
            a[1] = __float_as_uint(a1.x); a[3] = __float_as_uint(a1.y);
#pragma unroll
            for (int nt = 0; nt < 8; nt++) {
                unsigned b[2];
                float2 bv = *(const float2*)(bs + ((nt << 3) + g) * GSTR + kk + 2 * tig);
                b[0] = __float_as_uint(bv.x); b[1] = __float_as_uint(bv.y);
                mma8(acc[nt], a, b);
            }
        }
    }
    float* c0 = C + (size_t)(m0 + wrow + g) * N + n0;
    float* c1 = c0 + (size_t)8 * N;
#pragma unroll
    for (int nt = 0; nt < 8; nt++) {
        if (QOUT) {
            *(float2*)(c0 + (nt << 3) + (tig << 1)) = make_float2(tf(acc[nt][0]), tf(acc[nt][1]));
            *(float2*)(c1 + (nt << 3) + (tig << 1)) = make_float2(tf(acc[nt][2]), tf(acc[nt][3]));
        } else {
            *(float2*)(c0 + (nt << 3) + (tig << 1)) = make_float2(acc[nt][0], acc[nt][1]);
            *(float2*)(c1 + (nt << 3) + (tig << 1)) = make_float2(acc[nt][2], acc[nt][3]);
        }
    }

    if (BN) {
        // deterministic per-block BN partials over this block's 128 rows.
        // thread col partials (16 cols each: nt*8 + 2tig + j), rows g and g+8
        float ps[16], ps2[16];
#pragma unroll
        for (int nt = 0; nt < 8; nt++)
#pragma unroll
            for (int j = 0; j < 2; j++) {
                float v0 = acc[nt][j], v1 = acc[nt][j + 2];
                ps [nt * 2 + j] = v0 + v1;
                ps2[nt * 2 + j] = v0 * v0 + v1 * v1;
            }
        // reduce over g (lanes differing by 4,8,16) — fixed order, deterministic
#pragma unroll
        for (int off = 4; off < 32; off <<= 1)
#pragma unroll
            for (int i = 0; i < 16; i++) {
                ps [i] += __shfl_xor_sync(0xffffffffu, ps [i], off);
                ps2[i] += __shfl_xor_sync(0xffffffffu, ps2[i], off);
            }
        __syncthreads();               // all warps done reading As/Bs; reuse sm
        float2* red = (float2*)sm;     // [8 warps][64 cols]
        if (g == 0) {
#pragma unroll
            for (int nt = 0; nt < 8; nt++)
#pragma unroll
                for (int j = 0; j < 2; j++) {
                    int col = nt * 8 + 2 * tig + j;
                    red[warp * 64 + col] = make_float2(ps[nt * 2 + j], ps2[nt * 2 + j]);
                }
        }
        __syncthreads();
        if (tid < 64) {
            float s = 0.f, s2 = 0.f;
#pragma unroll
            for (int w = 0; w < 8; w++) {
                float2 v = red[w * 64 + tid];
                s += v.x; s2 += v.y;
            }
            g_ps [by * CIN + n0 + tid] = s;
            g_ps2[by * CIN + n0 + tid] = s2;
        }
    }
}

// merged projections: z=0 Q, z=1 K, z=2 V
__global__ __launch_bounds__(256) void gemm_proj(const float* __restrict__ qq,
                                                 const float* __restrict__ xq,
                                                 const float* __restrict__ wq,
                                                 const float* __restrict__ wk,
                                                 const float* __restrict__ wv,
                                                 float* __restrict__ Q,
                                                 float* __restrict__ K,
                                                 float* __restrict__ V) {
    extern __shared__ float sm[];
    const float* A; const float* W; float* C;
    if (blockIdx.z == 0)      { A = qq; W = wq; C = Q; }
    else if (blockIdx.z == 1) { A = xq; W = wk; C = K; }
    else                      { A = xq; W = wv; C = V; }
    gemm_core<true, false>(A, W, C, HD, CIN, blockIdx.y << 7, blockIdx.x << 6,
                           blockIdx.y, sm);
}

// output projection + fused BN partial sums
__global__ __launch_bounds__(256) void gemm_out(const float* __restrict__ A,
                                                const float* __restrict__ W,
                                                float* __restrict__ C) {
    extern __shared__ float sm[];
    gemm_core<false, true>(A, W, C, CIN, HD, blockIdx.y << 7, blockIdx.x << 6,
                           blockIdx.y, sm);
}

// ---------------- flash attention, cp.async double-buffered, paired-k S-phase ----
#define QSTR 68     // Qs/Ps stride (keeps PV 32-bit loads conflict-free)
#define KSTR 72     // Ks stride (keeps paired 64-bit loads conflict-free)
#define VSTR 72
__global__ __launch_bounds__(256) void attn2(const float* __restrict__ Q,
                                             const float* __restrict__ K,
                                             const float* __restrict__ V,
                                             float* __restrict__ O) {
    extern __shared__ float sm[];
    float* Qs = sm;                            // [128*68]; reused as Ps after hoist
    float* Kb = sm + 128 * QSTR;               // [2][64*72]
    float* Vb = Kb + 2 * 64 * KSTR;            // [2][64*72]
    float* Ps = Qs;

    const int tid = threadIdx.x, lane = tid & 31, warp = tid >> 5;
    const int g = lane >> 2, tig = lane & 3;
    const int b = blockIdx.z, h = blockIdx.y, q0 = blockIdx.x << 7;
    const int wrow = warp << 4;

    const float* Qb = Q + ((size_t)(b * SQ_ + q0)) * HD + h * 64;
    const float* Kbase = K + ((size_t)b * SE_) * HD + h * 64;
    const float* Vbase = V + ((size_t)b * SE_) * HD + h * 64;

    auto loadKV = [&](int buf, int t0) {
        float* dk = Kb + buf * 64 * KSTR;
        float* dv = Vb + buf * 64 * VSTR;
        for (int i = tid; i < 1024; i += 256) {
            int r = i >> 4, c4 = (i & 15) << 2;
            cp16(dk + r * KSTR + c4, Kbase + (size_t)(t0 + r) * HD + c4);
            cp16(dv + r * VSTR + c4, Vbase + (size_t)(t0 + r) * HD + c4);
        }
    };

    loadKV(0, 0); CP_COMMIT();

    // stage Q (already tf32-rounded + pre-scaled), hoist paired-k fragments
    for (int i = tid; i < 2048; i += 256) {
        int r = i >> 4, c4 = (i & 15) << 2;
        *(float4*)(Qs + r * QSTR + c4) = *(const float4*)(Qb + (size_t)r * HD + c4);
    }
    __syncthreads();

    unsigned qf[8][4];
#pragma unroll
    for (int kc = 0; kc < 8; kc++) {
        float2 v0 = *(const float2*)(Qs + (wrow + g) * QSTR + (kc << 3) + 2 * tig);
        float2 v1 = *(const float2*)(Qs + (wrow + g + 8) * QSTR + (kc << 3) + 2 * tig);
        qf[kc][0] = __float_as_uint(v0.x); qf[kc][2] = __float_as_uint(v0.y);
        qf[kc][1] = __float_as_uint(v1.x); qf[kc][3] = __float_as_uint(v1.y);
    }

    float mr0 = -1e30f, mr1 = -1e30f, l0 = 0.f, l1 = 0.f;
    float o[8][4];
#pragma unroll
    for (int nt = 0; nt < 8; nt++)
#pragma unroll
        for (int j = 0; j < 4; j++) o[nt][j] = 0.f;

    for (int ti = 0; ti < SE_ / 64; ti++) {
        CP_WAIT0();
        __syncthreads();   // KV[ti] visible; all warps done with other buf and Ps/Qs
        if (ti + 1 < SE_ / 64) { loadKV((ti + 1) & 1, (ti + 1) << 6); CP_COMMIT(); }
        const float* ks = Kb + (ti & 1) * 64 * KSTR;
        const float* vs = Vb + (ti & 1) * 64 * VSTR;

        // S = Q K^T, paired-k B fragments (LDS.64)
        float s[8][4];
#pragma unroll
        for (int nt = 0; nt < 8; nt++)
#pragma unroll
            for (int j = 0; j < 4; j++) s[nt][j] = 0.f;
#pragma unroll
        for (int kc = 0; kc < 8; kc++) {
#pragma unroll
            for (int nt = 0; nt < 8; nt++) {
                unsigned bb[2];
                float2 bv = *(const float2*)(ks + ((nt << 3) + g) * KSTR + (kc << 3) + 2 * tig);
                bb[0] = __float_as_uint(bv.x); bb[1] = __float_as_uint(bv.y);
                mma8(s[nt], qf[kc], bb);
            }
        }

        // online softmax (rows wrow+g and wrow+g+8)
        float mx0 = -1e30f, mx1 = -1e30f;
#pragma unroll
        for (int nt = 0; nt < 8; nt++) {
            mx0 = fmaxf(mx0, fmaxf(s[nt][0], s[nt][1]));
            mx1 = fmaxf(mx1, fmaxf(s[nt][2], s[nt][3]));
        }
        mx0 = fmaxf(mx0, __shfl_xor_sync(0xffffffffu, mx0, 1));
        mx0 = fmaxf(mx0, __shfl_xor_sync(0xffffffffu, mx0, 2));
        mx1 = fmaxf(mx1, __shfl_xor_sync(0xffffffffu, mx1, 1));
        mx1 = fmaxf(mx1, __shfl_xor_sync(0xffffffffu, mx1, 2));
        float nm0 = fmaxf(mr0, mx0), nm1 = fmaxf(mr1, mx1);
        float corr0 = __expf(mr0 - nm0), corr1 = __expf(mr1 - nm1);
        mr0 = nm0; mr1 = nm1;
        float sum0 = 0.f, sum1 = 0.f;
#pragma unroll
        for (int nt = 0; nt < 8; nt++) {
            s[nt][0] = __expf(s[nt][0] - nm0); sum0 += s[nt][0];
            s[nt][1] = __expf(s[nt][1] - nm0); sum0 += s[nt][1];
            s[nt][2] = __expf(s[nt][2] - nm1); sum1 += s[nt][2];
            s[nt][3] = __expf(s[nt][3] - nm1); sum1 += s[nt][3];
        }
        sum0 += __shfl_xor_sync(0xffffffffu, sum0, 1);
        sum0 += __shfl_xor_sync(0xffffffffu, sum0, 2);
        sum1 += __shfl_xor_sync(0xffffffffu, sum1, 1);
        sum1 += __shfl_xor_sync(0xffffffffu, sum1, 2);
        l0 = l0 * corr0 + sum0;
        l1 = l1 * corr1 + sum1;
#pragma unroll
        for (int nt = 0; nt < 8; nt++) {
            o[nt][0] *= corr0; o[nt][1] *= corr0;
            o[nt][2] *= corr1; o[nt][3] *= corr1;
        }

        // P -> smem (tf32 round), own 16 rows, consumed in-warp
        {
            float* p0 = Ps + (wrow + g) * QSTR + (tig << 1);
            float* p1 = p0 + 8 * QSTR;
#pragma unroll
            for (int nt = 0; nt < 8; nt++) {
                *(float2*)(p0 + (nt << 3)) = make_float2(tf(s[nt][0]), tf(s[nt][1]));
                *(float2*)(p1 + (nt << 3)) = make_float2(tf(s[nt][2]), tf(s[nt][3]));
            }
        }
        __syncwarp();

        // O += P V (standard k mapping; V fragments span rows -> unpaired)
#pragma unroll
        for (int kc = 0; kc < 8; kc++) {
            unsigned a[4];
            const float* ap = Ps + (wrow + g) * QSTR + (kc << 3) + tig;
            a[0] = __float_as_uint(ap[0]);
            a[1] = __float_as_uint(ap[8 * QSTR]);
            a[2] = __float_as_uint(ap[4]);
            a[3] = __float_as_uint(ap[8 * QSTR + 4]);
#pragma unroll
            for (int nt = 0; nt < 8; nt++) {
                unsigned bb[2];
                const float* bp = vs + ((kc << 3) + tig) * VSTR + (nt << 3) + g;
                bb[0] = __float_as_uint(bp[0]);
                bb[1] = __float_as_uint(bp[4 * VSTR]);
                mma8(o[nt], a, bb);
            }
        }
    }

    const float il0 = 1.f / l0, il1 = 1.f / l1;
    float* o0 = O + ((size_t)(b * SQ_ + q0 + wrow + g)) * HD + h * 64;
    float* o1 = o0 + (size_t)8 * HD;
#pragma unroll
    for (int nt = 0; nt < 8; nt++) {
        *(float2*)(o0 + (nt << 3) + (tig << 1)) = make_float2(tf(o[nt][0] * il0), tf(o[nt][1] * il0));
        *(float2*)(o1 + (nt << 3) + (tig << 1)) = make_float2(tf(o[nt][2] * il1), tf(o[nt][3] * il1));
    }
}

// ---------------- BN finalize + apply ----------------
__global__ void bn_final(const float* __restrict__ gamma, const float* __restrict__ beta) {
    int c = threadIdx.x;
    float s = 0.f, s2 = 0.f;
#pragma unroll 4
    for (int b2 = 0; b2 < 128; b2++) {
        s  += g_ps [b2 * CIN + c];
        s2 += g_ps2[b2 * CIN + c];
    }
    const float inv = 1.f / (float)MTOT;
    float mean = s * inv;
    float var  = s2 * inv - mean * mean;
    float rstd = rsqrtf(var + 1e-5f);
    float sc = rstd * gamma[c];
    g_scale[c] = sc;
    g_bias [c] = beta[c] - mean * sc;
}

__global__ void bn_apply(float* __restrict__ out) {
    __shared__ float ssc[CIN], sbi[CIN];
    ssc[threadIdx.x] = g_scale[threadIdx.x];
    sbi[threadIdx.x] = g_bias [threadIdx.x];
    __syncthreads();
    size_t i = (size_t)blockIdx.x * 256 + threadIdx.x;
    float4 v = *(const float4*)(g_P + i * 4);
    int c = (int)((i * 4) & (CIN - 1));
    float r[4] = {v.x, v.y, v.z, v.w};
#pragma unroll
    for (int u = 0; u < 4; u++) {
        float y = r[u] * ssc[c + u] + sbi[c + u];
        r[u] = y >= 0.f ? y : 0.01f * y;
    }
    *(float4*)(out + i * 4) = make_float4(r[0], r[1], r[2], r[3]);
}

// ---------------- launch ----------------
extern "C" void kernel_launch(void* const* d_in, const int* in_sizes, int n_in,
                              void* d_out, int out_size) {
    const float* x     = (const float*)d_in[0];
    const float* q     = (const float*)d_in[1];
    const float* Wq    = (const float*)d_in[2];
    const float* Wk    = (const float*)d_in[3];
    const float* Wv    = (const float*)d_in[4];
    const float* Wp    = (const float*)d_in[5];
    const float* gamma = (const float*)d_in[6];
    const float* beta  = (const float*)d_in[7];
    float* out = (float*)d_out;

    void *pQ, *pK, *pV, *pO, *pP, *pxq, *pqq, *pwq, *pwk, *pwv, *pwp;
    cudaGetSymbolAddress(&pQ, g_Q);   cudaGetSymbolAddress(&pK, g_K);
    cudaGetSymbolAddress(&pV, g_V);   cudaGetSymbolAddress(&pO, g_O);
    cudaGetSymbolAddress(&pP, g_P);   cudaGetSymbolAddress(&pxq, g_xq);
    cudaGetSymbolAddress(&pqq, g_qq); cudaGetSymbolAddress(&pwq, g_wq);
    cudaGetSymbolAddress(&pwk, g_wk); cudaGetSymbolAddress(&pwv, g_wv);
    cudaGetSymbolAddress(&pwp, g_wp);

    const int gemm_smem = (2 * 128 * GSTR + 2 * 64 * GSTR) * 4;              // 110592
    const int attn_smem = (128 * QSTR + 2 * 64 * KSTR + 2 * 64 * VSTR) * 4;  // 108544
    cudaFuncSetAttribute(gemm_proj, cudaFuncAttributeMaxDynamicSharedMemorySize, gemm_smem);
    cudaFuncSetAttribute(gemm_out,  cudaFuncAttributeMaxDynamicSharedMemorySize, gemm_smem);
    cudaFuncSetAttribute(attn2,     cudaFuncAttributeMaxDynamicSharedMemorySize, attn_smem);

    // single fused tf32 quantization pass (q folds 1/sqrt(DK) — exact)
    quant_all<<<(2 * NX4 + 4 * NW4) / 256, 256>>>(
        (const float4*)q, (const float4*)x, (const float4*)Wq, (const float4*)Wk,
        (const float4*)Wv, (const float4*)Wp,
        (float4*)pqq, (float4*)pxq, (float4*)pwq, (float4*)pwk,
        (float4*)pwv, (float4*)pwp);

    // merged Q/K/V projections: [16384,256] x [512,256]^T -> [16384,512]
    gemm_proj<<<dim3(HD / 64, MTOT / 128, 3), 256, gemm_smem>>>(
        (const float*)pqq, (const float*)pxq,
        (const float*)pwq, (const float*)pwk, (const float*)pwv,
        (float*)pQ, (float*)pK, (float*)pV);

    // attention
    attn2<<<dim3(SQ_ / 128, H_, B_), 256, attn_smem>>>(
        (const float*)pQ, (const float*)pK, (const float*)pV, (float*)pO);

    // output projection + fused BN partials: [16384,512] x [256,512]^T -> [16384,256]
    gemm_out<<<dim3(CIN / 64, MTOT / 128), 256, gemm_smem>>>(
        (const float*)pO, (const float*)pwp, (float*)pP);

    // BN finalize + apply
    bn_final<<<1, 256>>>(gamma, beta);
    bn_apply<<<(MTOT * CIN) / (4 * 256), 256>>>(out);
}